// round 2
// baseline (speedup 1.0000x reference)
#include <cuda_runtime.h>
#include <cstdint>

#define DEVINL __device__ __forceinline__

constexpr int B = 4, N = 4096, K = 10, BN = B * N;
constexpr float SLOPE = 0.2f;
constexpr float BNS = 0.9999950000374997f; // 1/sqrt(1+1e-5)
constexpr float NEG_INF = -3.4e38f;

// ---------------- scratch (static device globals; no allocation) ----------------
__device__ float g_cat[BN * 512];   // concatenated per-point features (o1|o2|o3|o4)
__device__ float g_AC[BN * 512];    // per-layer [A | C] activations (2O <= 512)
__device__ float g_sq[BN];          // squared norms
__device__ int   g_knn[BN * K];     // kNN indices (batch-local)
__device__ float g_wc[512 * 128];   // stacked weights [w1 ; w2-w1], padded to DPAD
__device__ float g_part[256 * 1024];// partial row-maxes for w5 stage
__device__ float g_h0[B * 1024];
__device__ float g_y1[B * 512];
__device__ float g_y2[B * 256];

DEVINL const float* x_resolve(const float* xext, int xoff) {
    return xext ? xext : (g_cat + xoff);
}

// ---------------- squared norms ----------------
__global__ void sqnorm_kernel(const float* __restrict__ xext, int xoff, int ldx, int D) {
    int i = blockIdx.x * blockDim.x + threadIdx.x;
    if (i >= BN) return;
    const float* x = x_resolve(xext, xoff);
    const float* p = x + (size_t)i * ldx;
    float s = 0.f;
    for (int d = 0; d < D; ++d) s += p[d] * p[d];
    g_sq[i] = s;
}

// ---------------- weight prep: wc = [w1 ; w2-w1] padded to DPAD ----------------
__global__ void prep_wc_kernel(const float* __restrict__ w, int O, int D, int DPAD) {
    int i = blockIdx.x * blockDim.x + threadIdx.x;
    int total = 2 * O * DPAD;
    if (i >= total) return;
    int r = i / DPAD, d = i % DPAD;
    float v = 0.f;
    if (d < D) {
        if (r < O) v = w[r * 2 * D + d];
        else { int o = r - O; v = w[o * 2 * D + D + d] - w[o * 2 * D + d]; }
    }
    g_wc[i] = v;
}

// ---------------- fused gram + top-k kNN ----------------
// block: 256 threads; tile: 64 queries x 32-candidate chunks, d in float4 vecs.
// Each thread computes a 4q x 2c dot micro-tile; scores are redistributed via
// SMEM so each thread streams candidates for exactly ONE query (top-10 list in
// registers), final 4-way merge of sorted lists per query.
template<int D, int DPAD>
__global__ void __launch_bounds__(256) knn_kernel(const float* __restrict__ xext, int xoff, int ldx) {
    constexpr int R4  = DPAD / 4;
    constexpr int SWM = (R4 >= 8) ? 7 : 0;
    constexpr int QBYTES = 64 * DPAD * 4;
    constexpr int MBYTES = 64 * 4 * K * 8;          // merge lists val+idx
    constexpr int QREG = (QBYTES > MBYTES) ? QBYTES : MBYTES;
    constexpr int CBYTES = 32 * DPAD * 4;
    constexpr int SBYTES = 64 * 33 * 4;             // padded score buffer
    constexpr int CREG = (CBYTES > SBYTES) ? CBYTES : SBYTES;
    __shared__ __align__(16) char smem[QREG + CREG];
    float4* Q4 = (float4*)smem;
    float4* C4 = (float4*)(smem + QREG);
    float*  Ss = (float*)(smem + QREG);
    float*  Mv = (float*)smem;
    int*    Mi = (int*)(smem + 64 * 4 * K * 4);

    const float* x = x_resolve(xext, xoff);
    int tid = threadIdx.x;
    int tx = tid & 15, ty = tid >> 4;
    int rq = tid & 63, rs = tid >> 6;
    int b = blockIdx.y, qbase = blockIdx.x * 64;
    const float* xb  = x + (size_t)b * N * ldx;
    const float* sqb = g_sq + b * N;
    int qglob = qbase + rq;

    float lv[K]; int li[K];
#pragma unroll
    for (int j = 0; j < K; ++j) { lv[j] = NEG_INF; li[j] = 0x7fffffff; }

    // load Q tile (64 x DPAD), xor-swizzled float4 rows
    if constexpr (D == 3) {
        for (int i = tid; i < 64; i += 256) {
            const float* p = xb + (size_t)(qbase + i) * ldx;
            Q4[i] = make_float4(p[0], p[1], p[2], 0.f);
        }
    } else {
        for (int i = tid; i < 64 * R4; i += 256) {
            int row = i / R4, dv = i % R4;
            Q4[row * R4 + (dv ^ (row & SWM))] =
                *(const float4*)(xb + (size_t)(qbase + row) * ldx + dv * 4);
        }
    }
    __syncthreads();

    for (int cb = 0; cb < N; cb += 32) {
        if constexpr (D == 3) {
            for (int i = tid; i < 32; i += 256) {
                const float* p = xb + (size_t)(cb + i) * ldx;
                C4[i] = make_float4(p[0], p[1], p[2], 0.f);
            }
        } else {
            for (int i = tid; i < 32 * R4; i += 256) {
                int row = i / R4, dv = i % R4;
                C4[row * R4 + (dv ^ (row & SWM))] =
                    *(const float4*)(xb + (size_t)(cb + row) * ldx + dv * 4);
            }
        }
        __syncthreads();

        float acc[4][2];
#pragma unroll
        for (int qi = 0; qi < 4; ++qi) { acc[qi][0] = 0.f; acc[qi][1] = 0.f; }
#pragma unroll
        for (int dv = 0; dv < R4; ++dv) {
            float4 qv[4], cv[2];
#pragma unroll
            for (int qi = 0; qi < 4; ++qi)
                qv[qi] = Q4[(ty + 16 * qi) * R4 + (dv ^ (ty & SWM))];
#pragma unroll
            for (int ci = 0; ci < 2; ++ci)
                cv[ci] = C4[(tx + 16 * ci) * R4 + (dv ^ (tx & SWM))];
#pragma unroll
            for (int qi = 0; qi < 4; ++qi)
#pragma unroll
                for (int ci = 0; ci < 2; ++ci)
                    acc[qi][ci] += qv[qi].x * cv[ci].x + qv[qi].y * cv[ci].y
                                 + qv[qi].z * cv[ci].z + qv[qi].w * cv[ci].w;
        }
        __syncthreads();  // done reading C4 before Ss overwrites it

        float sc0 = sqb[cb + tx], sc1 = sqb[cb + tx + 16];
#pragma unroll
        for (int qi = 0; qi < 4; ++qi) {
            Ss[(ty + 16 * qi) * 33 + tx]      = 2.f * acc[qi][0] - sc0;
            Ss[(ty + 16 * qi) * 33 + tx + 16] = 2.f * acc[qi][1] - sc1;
        }
        __syncthreads();

        // streaming top-k update: this thread owns query rq, candidates rs*8..rs*8+7
#pragma unroll
        for (int j = 0; j < 8; ++j) {
            int c = cb + rs * 8 + j;
            float v = Ss[rq * 33 + rs * 8 + j];
            if (c != qglob) {
                if (v > lv[K - 1] || (v == lv[K - 1] && c < li[K - 1])) {
                    float cvv = v; int cid = c;
#pragma unroll
                    for (int t = 0; t < K; ++t) {
                        bool better = (cvv > lv[t]) || (cvv == lv[t] && cid < li[t]);
                        float tv = lv[t]; int ti = li[t];
                        if (better) { lv[t] = cvv; li[t] = cid; cvv = tv; cid = ti; }
                    }
                }
            }
        }
        __syncthreads();
    }

    // merge the 4 sorted lists per query
#pragma unroll
    for (int j = 0; j < K; ++j) {
        Mv[(rq * 4 + rs) * K + j] = lv[j];
        Mi[(rq * 4 + rs) * K + j] = li[j];
    }
    __syncthreads();
    if (tid < 64) {
        int h[4] = {0, 0, 0, 0};
        int base = tid * 4 * K;
        int* out = g_knn + (size_t)(b * N + qbase + tid) * K;
        for (int j = 0; j < K; ++j) {
            float bv = NEG_INF; int bi = 0x7fffffff; int bs = 0;
#pragma unroll
            for (int s = 0; s < 4; ++s) {
                if (h[s] < K) {
                    float v = Mv[base + s * K + h[s]];
                    int   i = Mi[base + s * K + h[s]];
                    if (v > bv || (v == bv && i < bi)) { bv = v; bi = i; bs = s; }
                }
            }
            h[bs]++;
            out[j] = bi;
        }
    }
}

// ---------------- register-tiled GEMM (64x64 tile), optional fused w5 epilogue -----
// !W5MAX: out = X @ g_wc^T  into g_AC  (ldo = 2O)
//  W5MAX: h = X @ w5^T, bn+lrelu, per-64-row max -> g_part
template<int DPAD, bool W5MAX>
__global__ void __launch_bounds__(256) gemm_kernel(
    const float* __restrict__ xext, int xoff, int ldx,
    const float* __restrict__ wext, int ldw, int ldo,
    const float* __restrict__ gg, const float* __restrict__ bb)
{
    constexpr int DC  = (DPAD < 64) ? DPAD : 64;
    constexpr int RC  = DC / 4;
    constexpr int SWM = (RC >= 8) ? 7 : 0;
    __shared__ float4 Xs[64 * RC];
    __shared__ float4 Ws[64 * RC];
    const float* x = x_resolve(xext, xoff);
    const float* w = W5MAX ? wext : g_wc;
    int tid = threadIdx.x, tx = tid & 15, ty = tid >> 4;
    int rowbase = blockIdx.x * 64, colbase = blockIdx.y * 64;
    float acc[4][4];
#pragma unroll
    for (int qi = 0; qi < 4; ++qi)
#pragma unroll
        for (int ci = 0; ci < 4; ++ci) acc[qi][ci] = 0.f;

    for (int ch = 0; ch < DPAD / DC; ++ch) {
        int d0 = ch * DC;
        if constexpr (DPAD == 4) {
            for (int i = tid; i < 64; i += 256) {
                const float* p = x + (size_t)(rowbase + i) * ldx;
                Xs[i] = make_float4(p[0], p[1], p[2], 0.f);
            }
        } else {
            for (int i = tid; i < 64 * RC; i += 256) {
                int r = i / RC, dv = i % RC;
                Xs[r * RC + (dv ^ (r & SWM))] =
                    *(const float4*)(x + (size_t)(rowbase + r) * ldx + d0 + 4 * dv);
            }
        }
        for (int i = tid; i < 64 * RC; i += 256) {
            int r = i / RC, dv = i % RC;
            Ws[r * RC + (dv ^ (r & SWM))] =
                *(const float4*)(w + (size_t)(colbase + r) * ldw + d0 + 4 * dv);
        }
        __syncthreads();
#pragma unroll
        for (int dv = 0; dv < RC; ++dv) {
            float4 xv[4], wv[4];
#pragma unroll
            for (int qi = 0; qi < 4; ++qi)
                xv[qi] = Xs[(ty + 16 * qi) * RC + (dv ^ (ty & SWM))];
#pragma unroll
            for (int ci = 0; ci < 4; ++ci)
                wv[ci] = Ws[(tx + 16 * ci) * RC + (dv ^ (tx & SWM))];
#pragma unroll
            for (int qi = 0; qi < 4; ++qi)
#pragma unroll
                for (int ci = 0; ci < 4; ++ci)
                    acc[qi][ci] += xv[qi].x * wv[ci].x + xv[qi].y * wv[ci].y
                                 + xv[qi].z * wv[ci].z + xv[qi].w * wv[ci].w;
        }
        __syncthreads();
    }

    if constexpr (!W5MAX) {
#pragma unroll
        for (int qi = 0; qi < 4; ++qi)
#pragma unroll
            for (int ci = 0; ci < 4; ++ci)
                g_AC[(size_t)(rowbase + ty + 16 * qi) * ldo + colbase + tx + 16 * ci] = acc[qi][ci];
    } else {
        float cm[4];
#pragma unroll
        for (int ci = 0; ci < 4; ++ci) {
            int col = colbase + tx + 16 * ci;
            float g = BNS * gg[col], be = bb[col];
            float m = NEG_INF;
#pragma unroll
            for (int qi = 0; qi < 4; ++qi) {
                float v = g * acc[qi][ci] + be;
                v = (v > 0.f) ? v : SLOPE * v;
                m = fmaxf(m, v);
            }
            cm[ci] = m;
        }
        float* R = (float*)Xs;  // 16x64 floats, fits
#pragma unroll
        for (int ci = 0; ci < 4; ++ci) R[ty * 64 + tx + 16 * ci] = cm[ci];
        __syncthreads();
        if (tid < 64) {
            float m = R[tid];
#pragma unroll
            for (int t = 1; t < 16; ++t) m = fmaxf(m, R[t * 64 + tid]);
            g_part[(size_t)blockIdx.x * 1024 + colbase + tid] = m;
        }
    }
}

// ---------------- gather + bn + lrelu + max over k neighbors ----------------
__global__ void edgemax_kernel(const float* __restrict__ gamma, const float* __restrict__ beta,
                               int O, int catoff) {
    int n = blockIdx.x;          // global point row (0..BN-1)
    int o = threadIdx.x;
    int b = n >> 12;
    __shared__ int sidx[K];
    if (o < K) sidx[o] = g_knn[(size_t)n * K + o];
    __syncthreads();
    int twoO = 2 * O;
    float cterm = g_AC[(size_t)n * twoO + O + o];
    float g = BNS * gamma[o], be = beta[o];
    int base = b << 12;
    float m = NEG_INF;
#pragma unroll
    for (int j = 0; j < K; ++j) {
        float a = g_AC[(size_t)(base + sidx[j]) * twoO + o];
        float v = g * (a + cterm) + be;
        v = (v > 0.f) ? v : SLOPE * v;
        m = fmaxf(m, v);
    }
    g_cat[(size_t)n * 512 + catoff + o] = m;
}

// ---------------- final max reduce + MLP head ----------------
__global__ void maxreduce_kernel() {
    int i = blockIdx.x * blockDim.x + threadIdx.x;
    if (i >= B * 1024) return;
    int b = i / 1024, o = i % 1024;
    float m = NEG_INF;
    for (int j = 0; j < 64; ++j)
        m = fmaxf(m, g_part[(size_t)(b * 64 + j) * 1024 + o]);
    g_h0[i] = m;
}

__global__ void fc1_kernel(const float* __restrict__ fw1, const float* __restrict__ fg1,
                           const float* __restrict__ fbt1) {
    int t = blockIdx.x * blockDim.x + threadIdx.x;
    if (t >= B * 512) return;
    int b = t / 512, o = t % 512;
    const float* h = g_h0 + b * 1024;
    const float* wr = fw1 + (size_t)o * 1024;
    float s = 0.f;
    for (int c = 0; c < 1024; ++c) s += h[c] * wr[c];
    float v = BNS * fg1[o] * s + fbt1[o];
    g_y1[t] = (v > 0.f) ? v : SLOPE * v;
}

__global__ void fc2_kernel(const float* __restrict__ fw2, const float* __restrict__ fb2,
                           const float* __restrict__ fg2, const float* __restrict__ fbt2) {
    int t = blockIdx.x * blockDim.x + threadIdx.x;
    if (t >= B * 256) return;
    int b = t / 256, o = t % 256;
    const float* h = g_y1 + b * 512;
    const float* wr = fw2 + (size_t)o * 512;
    float s = 0.f;
    for (int c = 0; c < 512; ++c) s += h[c] * wr[c];
    float v = BNS * fg2[o] * (s + fb2[o]) + fbt2[o];
    g_y2[t] = (v > 0.f) ? v : SLOPE * v;
}

__global__ void fc3_kernel(const float* __restrict__ fw3, const float* __restrict__ fb3,
                           float* __restrict__ out) {
    int t = blockIdx.x * blockDim.x + threadIdx.x;
    if (t >= B * 3) return;
    int b = t / 3, o = t % 3;
    const float* h = g_y2 + b * 256;
    const float* wr = fw3 + (size_t)o * 256;
    float s = 0.f;
    for (int c = 0; c < 256; ++c) s += h[c] * wr[c];
    out[t] = s + fb3[o];
}

// ---------------- launch ----------------
extern "C" void kernel_launch(void* const* d_in, const int* in_sizes, int n_in,
                              void* d_out, int out_size) {
    const float* points = (const float*)d_in[0];
    // d_in[1] = k (always 10)
    const float* w1 = (const float*)d_in[2];
    const float* g1 = (const float*)d_in[3];
    const float* b1 = (const float*)d_in[4];
    const float* w2 = (const float*)d_in[5];
    const float* g2 = (const float*)d_in[6];
    const float* b2 = (const float*)d_in[7];
    const float* w3 = (const float*)d_in[8];
    const float* g3 = (const float*)d_in[9];
    const float* b3 = (const float*)d_in[10];
    const float* w4 = (const float*)d_in[11];
    const float* g4 = (const float*)d_in[12];
    const float* b4 = (const float*)d_in[13];
    const float* w5 = (const float*)d_in[14];
    const float* g5 = (const float*)d_in[15];
    const float* b5 = (const float*)d_in[16];
    const float* fw1 = (const float*)d_in[17];
    const float* fg1 = (const float*)d_in[18];
    const float* fbt1 = (const float*)d_in[19];
    const float* fw2 = (const float*)d_in[20];
    const float* fb2 = (const float*)d_in[21];
    const float* fg2 = (const float*)d_in[22];
    const float* fbt2 = (const float*)d_in[23];
    const float* fw3 = (const float*)d_in[24];
    const float* fb3 = (const float*)d_in[25];
    float* out = (float*)d_out;

    dim3 knngrid(N / 64, B);

    // ---- EdgeConv 1: x = points (ld 3, D=3), O=64, cat cols [0,64)
    sqnorm_kernel<<<BN / 256, 256>>>(points, 0, 3, 3);
    knn_kernel<3, 4><<<knngrid, 256>>>(points, 0, 3);
    prep_wc_kernel<<<(2 * 64 * 4 + 255) / 256, 256>>>(w1, 64, 3, 4);
    gemm_kernel<4, false><<<dim3(BN / 64, 2), 256>>>(points, 0, 3, nullptr, 4, 128, nullptr, nullptr);
    edgemax_kernel<<<BN, 64>>>(g1, b1, 64, 0);

    // ---- EdgeConv 2: x = cat[:,0:64], O=64, cat cols [64,128)
    sqnorm_kernel<<<BN / 256, 256>>>(nullptr, 0, 512, 64);
    knn_kernel<64, 64><<<knngrid, 256>>>(nullptr, 0, 512);
    prep_wc_kernel<<<(2 * 64 * 64 + 255) / 256, 256>>>(w2, 64, 64, 64);
    gemm_kernel<64, false><<<dim3(BN / 64, 2), 256>>>(nullptr, 0, 512, nullptr, 64, 128, nullptr, nullptr);
    edgemax_kernel<<<BN, 64>>>(g2, b2, 64, 64);

    // ---- EdgeConv 3: x = cat[:,64:128], O=128, cat cols [128,256)
    sqnorm_kernel<<<BN / 256, 256>>>(nullptr, 64, 512, 64);
    knn_kernel<64, 64><<<knngrid, 256>>>(nullptr, 64, 512);
    prep_wc_kernel<<<(2 * 128 * 64 + 255) / 256, 256>>>(w3, 128, 64, 64);
    gemm_kernel<64, false><<<dim3(BN / 64, 4), 256>>>(nullptr, 64, 512, nullptr, 64, 256, nullptr, nullptr);
    edgemax_kernel<<<BN, 128>>>(g3, b3, 128, 128);

    // ---- EdgeConv 4: x = cat[:,128:256], D=128, O=256, cat cols [256,512)
    sqnorm_kernel<<<BN / 256, 256>>>(nullptr, 128, 512, 128);
    knn_kernel<128, 128><<<knngrid, 256>>>(nullptr, 128, 512);
    prep_wc_kernel<<<(2 * 256 * 128 + 255) / 256, 256>>>(w4, 256, 128, 128);
    gemm_kernel<128, false><<<dim3(BN / 64, 8), 256>>>(nullptr, 128, 512, nullptr, 128, 512, nullptr, nullptr);
    edgemax_kernel<<<BN, 256>>>(g4, b4, 256, 256);

    // ---- w5 GEMM (16384x512x1024) + bn + lrelu + row-block max
    gemm_kernel<512, true><<<dim3(BN / 64, 16), 256>>>(nullptr, 0, 512, w5, 512, 0, g5, b5);
    maxreduce_kernel<<<(B * 1024 + 255) / 256, 256>>>();

    // ---- MLP head
    fc1_kernel<<<(B * 512 + 255) / 256, 256>>>(fw1, fg1, fbt1);
    fc2_kernel<<<(B * 256 + 255) / 256, 256>>>(fw2, fb2, fg2, fbt2);
    fc3_kernel<<<1, 32>>>(fw3, fb3, out);
}

// round 3
// speedup vs baseline: 1.1160x; 1.1160x over previous
#include <cuda_runtime.h>
#include <cstdint>

#define DEVINL __device__ __forceinline__

constexpr int B = 4, N = 4096, K = 10, BN = B * N;
constexpr float SLOPE = 0.2f;
constexpr float BNS = 0.9999950000374997f; // 1/sqrt(1+1e-5)
constexpr float NEG_INF = -3.4e38f;

// packed fp32x2 FMA: acc.lo += a.lo*b.lo, acc.hi += a.hi*b.hi (one issue slot)
DEVINL void fma2(unsigned long long& acc, unsigned long long a, unsigned long long b) {
    asm("fma.rn.f32x2 %0, %1, %2, %0;" : "+l"(acc) : "l"(a), "l"(b));
}
DEVINL float f2sum(unsigned long long v) {
    float2 f; f = *reinterpret_cast<float2*>(&v);
    return f.x + f.y;
}
struct U64x2 { unsigned long long a, b; };
DEVINL U64x2 asu64x2(const float4& v) {
    U64x2 r;
    r.a = *reinterpret_cast<const unsigned long long*>(&v.x);
    r.b = *reinterpret_cast<const unsigned long long*>(&v.z);
    return r;
}

// ---------------- scratch (static device globals; no allocation) ----------------
__device__ float g_cat[BN * 512];   // concatenated per-point features (o1|o2|o3|o4)
__device__ float g_AC[BN * 512];    // per-layer [A | C] activations (2O <= 512)
__device__ float g_sq[BN];          // squared norms
__device__ int   g_knn[BN * K];     // kNN indices (batch-local)
__device__ float g_wc[512 * 128];   // stacked weights [w1 ; w2-w1], padded to DPAD
__device__ float g_part[256 * 1024];// partial row-maxes for w5 stage
__device__ float g_h0[B * 1024];
__device__ float g_y1[B * 512];
__device__ float g_y2[B * 256];

DEVINL const float* x_resolve(const float* xext, int xoff) {
    return xext ? xext : (g_cat + xoff);
}

// ---------------- squared norms ----------------
__global__ void sqnorm_kernel(const float* __restrict__ xext, int xoff, int ldx, int D) {
    int i = blockIdx.x * blockDim.x + threadIdx.x;
    if (i >= BN) return;
    const float* x = x_resolve(xext, xoff);
    const float* p = x + (size_t)i * ldx;
    float s = 0.f;
    for (int d = 0; d < D; ++d) s += p[d] * p[d];
    g_sq[i] = s;
}

// ---------------- weight prep: wc = [w1 ; w2-w1] padded to DPAD ----------------
__global__ void prep_wc_kernel(const float* __restrict__ w, int O, int D, int DPAD) {
    int i = blockIdx.x * blockDim.x + threadIdx.x;
    int total = 2 * O * DPAD;
    if (i >= total) return;
    int r = i / DPAD, d = i % DPAD;
    float v = 0.f;
    if (d < D) {
        if (r < O) v = w[r * 2 * D + d];
        else { int o = r - O; v = w[o * 2 * D + D + d] - w[o * 2 * D + d]; }
    }
    g_wc[i] = v;
}

// ---------------- fused gram + top-k kNN ----------------
// block: 256 threads; tile: 64 queries x 32-candidate chunks.
// Gram micro-tile per thread: 4q x 2c, reduction dim packed in f32x2 lanes.
template<int D, int DPAD>
__global__ void __launch_bounds__(256) knn_kernel(const float* __restrict__ xext, int xoff, int ldx) {
    constexpr int R4  = DPAD / 4;
    constexpr int SWM = (R4 >= 8) ? 7 : 0;
    constexpr int QBYTES = 64 * DPAD * 4;
    constexpr int MBYTES = 64 * 4 * K * 8;          // merge lists val+idx
    constexpr int QREG = (QBYTES > MBYTES) ? QBYTES : MBYTES;
    constexpr int CBYTES = 32 * DPAD * 4;
    constexpr int SBYTES = 64 * 33 * 4;             // padded score buffer
    constexpr int CREG = (CBYTES > SBYTES) ? CBYTES : SBYTES;
    __shared__ __align__(16) char smem[QREG + CREG];
    float4* Q4 = (float4*)smem;
    float4* C4 = (float4*)(smem + QREG);
    float*  Ss = (float*)(smem + QREG);
    float*  Mv = (float*)smem;
    int*    Mi = (int*)(smem + 64 * 4 * K * 4);

    const float* x = x_resolve(xext, xoff);
    int tid = threadIdx.x;
    int tx = tid & 15, ty = tid >> 4;
    int rq = tid & 63, rs = tid >> 6;
    int b = blockIdx.y, qbase = blockIdx.x * 64;
    const float* xb  = x + (size_t)b * N * ldx;
    const float* sqb = g_sq + b * N;
    int qglob = qbase + rq;

    float lv[K]; int li[K];
#pragma unroll
    for (int j = 0; j < K; ++j) { lv[j] = NEG_INF; li[j] = 0x7fffffff; }

    // load Q tile (64 x DPAD), xor-swizzled float4 rows
    if constexpr (D == 3) {
        for (int i = tid; i < 64; i += 256) {
            const float* p = xb + (size_t)(qbase + i) * ldx;
            Q4[i] = make_float4(p[0], p[1], p[2], 0.f);
        }
    } else {
        for (int i = tid; i < 64 * R4; i += 256) {
            int row = i / R4, dv = i % R4;
            Q4[row * R4 + (dv ^ (row & SWM))] =
                *(const float4*)(xb + (size_t)(qbase + row) * ldx + dv * 4);
        }
    }
    __syncthreads();

    for (int cb = 0; cb < N; cb += 32) {
        if constexpr (D == 3) {
            for (int i = tid; i < 32; i += 256) {
                const float* p = xb + (size_t)(cb + i) * ldx;
                C4[i] = make_float4(p[0], p[1], p[2], 0.f);
            }
        } else {
            for (int i = tid; i < 32 * R4; i += 256) {
                int row = i / R4, dv = i % R4;
                C4[row * R4 + (dv ^ (row & SWM))] =
                    *(const float4*)(xb + (size_t)(cb + row) * ldx + dv * 4);
            }
        }
        __syncthreads();

        unsigned long long acc2[4][2];
#pragma unroll
        for (int qi = 0; qi < 4; ++qi) { acc2[qi][0] = 0ull; acc2[qi][1] = 0ull; }
#pragma unroll
        for (int dv = 0; dv < R4; ++dv) {
            U64x2 qv[4], cv[2];
#pragma unroll
            for (int qi = 0; qi < 4; ++qi)
                qv[qi] = asu64x2(Q4[(ty + 16 * qi) * R4 + (dv ^ (ty & SWM))]);
#pragma unroll
            for (int ci = 0; ci < 2; ++ci)
                cv[ci] = asu64x2(C4[(tx + 16 * ci) * R4 + (dv ^ (tx & SWM))]);
#pragma unroll
            for (int qi = 0; qi < 4; ++qi)
#pragma unroll
                for (int ci = 0; ci < 2; ++ci) {
                    fma2(acc2[qi][ci], qv[qi].a, cv[ci].a);
                    fma2(acc2[qi][ci], qv[qi].b, cv[ci].b);
                }
        }
        __syncthreads();  // done reading C4 before Ss overwrites it

        float sc0 = sqb[cb + tx], sc1 = sqb[cb + tx + 16];
#pragma unroll
        for (int qi = 0; qi < 4; ++qi) {
            Ss[(ty + 16 * qi) * 33 + tx]      = 2.f * f2sum(acc2[qi][0]) - sc0;
            Ss[(ty + 16 * qi) * 33 + tx + 16] = 2.f * f2sum(acc2[qi][1]) - sc1;
        }
        __syncthreads();

        // streaming top-k update: this thread owns query rq, candidates rs*8..rs*8+7
#pragma unroll
        for (int j = 0; j < 8; ++j) {
            int c = cb + rs * 8 + j;
            float v = Ss[rq * 33 + rs * 8 + j];
            if (c != qglob) {
                if (v > lv[K - 1] || (v == lv[K - 1] && c < li[K - 1])) {
                    float cvv = v; int cid = c;
#pragma unroll
                    for (int t = 0; t < K; ++t) {
                        bool better = (cvv > lv[t]) || (cvv == lv[t] && cid < li[t]);
                        float tv = lv[t]; int ti = li[t];
                        if (better) { lv[t] = cvv; li[t] = cid; cvv = tv; cid = ti; }
                    }
                }
            }
        }
        __syncthreads();
    }

    // merge the 4 sorted lists per query
#pragma unroll
    for (int j = 0; j < K; ++j) {
        Mv[(rq * 4 + rs) * K + j] = lv[j];
        Mi[(rq * 4 + rs) * K + j] = li[j];
    }
    __syncthreads();
    if (tid < 64) {
        int h[4] = {0, 0, 0, 0};
        int base = tid * 4 * K;
        int* out = g_knn + (size_t)(b * N + qbase + tid) * K;
        for (int j = 0; j < K; ++j) {
            float bv = NEG_INF; int bi = 0x7fffffff; int bs = 0;
#pragma unroll
            for (int s = 0; s < 4; ++s) {
                if (h[s] < K) {
                    float v = Mv[base + s * K + h[s]];
                    int   i = Mi[base + s * K + h[s]];
                    if (v > bv || (v == bv && i < bi)) { bv = v; bi = i; bs = s; }
                }
            }
            h[bs]++;
            out[j] = bi;
        }
    }
}

// ---------------- register-tiled GEMM (64x64 tile), optional fused w5 epilogue -----
// !W5MAX: out = X @ g_wc^T  into g_AC  (ldo = 2O)
//  W5MAX: h = X @ w5^T, bn+lrelu, per-64-row max -> g_part
template<int DPAD, bool W5MAX>
__global__ void __launch_bounds__(256) gemm_kernel(
    const float* __restrict__ xext, int xoff, int ldx,
    const float* __restrict__ wext, int ldw, int ldo,
    const float* __restrict__ gg, const float* __restrict__ bb)
{
    constexpr int DC  = (DPAD < 64) ? DPAD : 64;
    constexpr int RC  = DC / 4;
    constexpr int SWM = (RC >= 8) ? 7 : 0;
    __shared__ float4 Xs[64 * RC];
    __shared__ float4 Ws[64 * RC];
    const float* x = x_resolve(xext, xoff);
    const float* w = W5MAX ? wext : g_wc;
    int tid = threadIdx.x, tx = tid & 15, ty = tid >> 4;
    int rowbase = blockIdx.x * 64, colbase = blockIdx.y * 64;
    unsigned long long acc2[4][4];
#pragma unroll
    for (int qi = 0; qi < 4; ++qi)
#pragma unroll
        for (int ci = 0; ci < 4; ++ci) acc2[qi][ci] = 0ull;

    for (int ch = 0; ch < DPAD / DC; ++ch) {
        int d0 = ch * DC;
        if constexpr (DPAD == 4) {
            for (int i = tid; i < 64; i += 256) {
                const float* p = x + (size_t)(rowbase + i) * ldx;
                Xs[i] = make_float4(p[0], p[1], p[2], 0.f);
            }
        } else {
            for (int i = tid; i < 64 * RC; i += 256) {
                int r = i / RC, dv = i % RC;
                Xs[r * RC + (dv ^ (r & SWM))] =
                    *(const float4*)(x + (size_t)(rowbase + r) * ldx + d0 + 4 * dv);
            }
        }
        for (int i = tid; i < 64 * RC; i += 256) {
            int r = i / RC, dv = i % RC;
            Ws[r * RC + (dv ^ (r & SWM))] =
                *(const float4*)(w + (size_t)(colbase + r) * ldw + d0 + 4 * dv);
        }
        __syncthreads();
#pragma unroll
        for (int dv = 0; dv < RC; ++dv) {
            U64x2 xv[4], wv[4];
#pragma unroll
            for (int qi = 0; qi < 4; ++qi)
                xv[qi] = asu64x2(Xs[(ty + 16 * qi) * RC + (dv ^ (ty & SWM))]);
#pragma unroll
            for (int ci = 0; ci < 4; ++ci)
                wv[ci] = asu64x2(Ws[(tx + 16 * ci) * RC + (dv ^ (tx & SWM))]);
#pragma unroll
            for (int qi = 0; qi < 4; ++qi)
#pragma unroll
                for (int ci = 0; ci < 4; ++ci) {
                    fma2(acc2[qi][ci], xv[qi].a, wv[ci].a);
                    fma2(acc2[qi][ci], xv[qi].b, wv[ci].b);
                }
        }
        __syncthreads();
    }

    if constexpr (!W5MAX) {
#pragma unroll
        for (int qi = 0; qi < 4; ++qi)
#pragma unroll
            for (int ci = 0; ci < 4; ++ci)
                g_AC[(size_t)(rowbase + ty + 16 * qi) * ldo + colbase + tx + 16 * ci] =
                    f2sum(acc2[qi][ci]);
    } else {
        float cm[4];
#pragma unroll
        for (int ci = 0; ci < 4; ++ci) {
            int col = colbase + tx + 16 * ci;
            float g = BNS * gg[col], be = bb[col];
            float m = NEG_INF;
#pragma unroll
            for (int qi = 0; qi < 4; ++qi) {
                float v = g * f2sum(acc2[qi][ci]) + be;
                v = (v > 0.f) ? v : SLOPE * v;
                m = fmaxf(m, v);
            }
            cm[ci] = m;
        }
        float* R = (float*)Xs;  // 16x64 floats, fits
#pragma unroll
        for (int ci = 0; ci < 4; ++ci) R[ty * 64 + tx + 16 * ci] = cm[ci];
        __syncthreads();
        if (tid < 64) {
            float m = R[tid];
#pragma unroll
            for (int t = 1; t < 16; ++t) m = fmaxf(m, R[t * 64 + tid]);
            g_part[(size_t)blockIdx.x * 1024 + colbase + tid] = m;
        }
    }
}

// ---------------- gather + bn + lrelu + max over k neighbors ----------------
__global__ void edgemax_kernel(const float* __restrict__ gamma, const float* __restrict__ beta,
                               int O, int catoff) {
    int n = blockIdx.x;          // global point row (0..BN-1)
    int o = threadIdx.x;
    int b = n >> 12;
    __shared__ int sidx[K];
    if (o < K) sidx[o] = g_knn[(size_t)n * K + o];
    __syncthreads();
    int twoO = 2 * O;
    float cterm = g_AC[(size_t)n * twoO + O + o];
    float g = BNS * gamma[o], be = beta[o];
    int base = b << 12;
    float m = NEG_INF;
#pragma unroll
    for (int j = 0; j < K; ++j) {
        float a = g_AC[(size_t)(base + sidx[j]) * twoO + o];
        float v = g * (a + cterm) + be;
        v = (v > 0.f) ? v : SLOPE * v;
        m = fmaxf(m, v);
    }
    g_cat[(size_t)n * 512 + catoff + o] = m;
}

// ---------------- final max reduce + MLP head ----------------
__global__ void maxreduce_kernel() {
    int i = blockIdx.x * blockDim.x + threadIdx.x;
    if (i >= B * 1024) return;
    int b = i / 1024, o = i % 1024;
    float m = NEG_INF;
    for (int j = 0; j < 64; ++j)
        m = fmaxf(m, g_part[(size_t)(b * 64 + j) * 1024 + o]);
    g_h0[i] = m;
}

__global__ void fc1_kernel(const float* __restrict__ fw1, const float* __restrict__ fg1,
                           const float* __restrict__ fbt1) {
    int t = blockIdx.x * blockDim.x + threadIdx.x;
    if (t >= B * 512) return;
    int b = t / 512, o = t % 512;
    const float* h = g_h0 + b * 1024;
    const float* wr = fw1 + (size_t)o * 1024;
    float s = 0.f;
    for (int c = 0; c < 1024; ++c) s += h[c] * wr[c];
    float v = BNS * fg1[o] * s + fbt1[o];
    g_y1[t] = (v > 0.f) ? v : SLOPE * v;
}

__global__ void fc2_kernel(const float* __restrict__ fw2, const float* __restrict__ fb2,
                           const float* __restrict__ fg2, const float* __restrict__ fbt2) {
    int t = blockIdx.x * blockDim.x + threadIdx.x;
    if (t >= B * 256) return;
    int b = t / 256, o = t % 256;
    const float* h = g_y1 + b * 512;
    const float* wr = fw2 + (size_t)o * 512;
    float s = 0.f;
    for (int c = 0; c < 512; ++c) s += h[c] * wr[c];
    float v = BNS * fg2[o] * (s + fb2[o]) + fbt2[o];
    g_y2[t] = (v > 0.f) ? v : SLOPE * v;
}

__global__ void fc3_kernel(const float* __restrict__ fw3, const float* __restrict__ fb3,
                           float* __restrict__ out) {
    int t = blockIdx.x * blockDim.x + threadIdx.x;
    if (t >= B * 3) return;
    int b = t / 3, o = t % 3;
    const float* h = g_y2 + b * 256;
    const float* wr = fw3 + (size_t)o * 256;
    float s = 0.f;
    for (int c = 0; c < 256; ++c) s += h[c] * wr[c];
    out[t] = s + fb3[o];
}

// ---------------- launch ----------------
extern "C" void kernel_launch(void* const* d_in, const int* in_sizes, int n_in,
                              void* d_out, int out_size) {
    const float* points = (const float*)d_in[0];
    // d_in[1] = k (always 10)
    const float* w1 = (const float*)d_in[2];
    const float* g1 = (const float*)d_in[3];
    const float* b1 = (const float*)d_in[4];
    const float* w2 = (const float*)d_in[5];
    const float* g2 = (const float*)d_in[6];
    const float* b2 = (const float*)d_in[7];
    const float* w3 = (const float*)d_in[8];
    const float* g3 = (const float*)d_in[9];
    const float* b3 = (const float*)d_in[10];
    const float* w4 = (const float*)d_in[11];
    const float* g4 = (const float*)d_in[12];
    const float* b4 = (const float*)d_in[13];
    const float* w5 = (const float*)d_in[14];
    const float* g5 = (const float*)d_in[15];
    const float* b5 = (const float*)d_in[16];
    const float* fw1 = (const float*)d_in[17];
    const float* fg1 = (const float*)d_in[18];
    const float* fbt1 = (const float*)d_in[19];
    const float* fw2 = (const float*)d_in[20];
    const float* fb2 = (const float*)d_in[21];
    const float* fg2 = (const float*)d_in[22];
    const float* fbt2 = (const float*)d_in[23];
    const float* fw3 = (const float*)d_in[24];
    const float* fb3 = (const float*)d_in[25];
    float* out = (float*)d_out;

    dim3 knngrid(N / 64, B);

    // ---- EdgeConv 1: x = points (ld 3, D=3), O=64, cat cols [0,64)
    sqnorm_kernel<<<BN / 256, 256>>>(points, 0, 3, 3);
    knn_kernel<3, 4><<<knngrid, 256>>>(points, 0, 3);
    prep_wc_kernel<<<(2 * 64 * 4 + 255) / 256, 256>>>(w1, 64, 3, 4);
    gemm_kernel<4, false><<<dim3(BN / 64, 2), 256>>>(points, 0, 3, nullptr, 4, 128, nullptr, nullptr);
    edgemax_kernel<<<BN, 64>>>(g1, b1, 64, 0);

    // ---- EdgeConv 2: x = cat[:,0:64], O=64, cat cols [64,128)
    sqnorm_kernel<<<BN / 256, 256>>>(nullptr, 0, 512, 64);
    knn_kernel<64, 64><<<knngrid, 256>>>(nullptr, 0, 512);
    prep_wc_kernel<<<(2 * 64 * 64 + 255) / 256, 256>>>(w2, 64, 64, 64);
    gemm_kernel<64, false><<<dim3(BN / 64, 2), 256>>>(nullptr, 0, 512, nullptr, 64, 128, nullptr, nullptr);
    edgemax_kernel<<<BN, 64>>>(g2, b2, 64, 64);

    // ---- EdgeConv 3: x = cat[:,64:128], O=128, cat cols [128,256)
    sqnorm_kernel<<<BN / 256, 256>>>(nullptr, 64, 512, 64);
    knn_kernel<64, 64><<<knngrid, 256>>>(nullptr, 64, 512);
    prep_wc_kernel<<<(2 * 128 * 64 + 255) / 256, 256>>>(w3, 128, 64, 64);
    gemm_kernel<64, false><<<dim3(BN / 64, 4), 256>>>(nullptr, 64, 512, nullptr, 64, 256, nullptr, nullptr);
    edgemax_kernel<<<BN, 128>>>(g3, b3, 128, 128);

    // ---- EdgeConv 4: x = cat[:,128:256], D=128, O=256, cat cols [256,512)
    sqnorm_kernel<<<BN / 256, 256>>>(nullptr, 128, 512, 128);
    knn_kernel<128, 128><<<knngrid, 256>>>(nullptr, 128, 512);
    prep_wc_kernel<<<(2 * 256 * 128 + 255) / 256, 256>>>(w4, 256, 128, 128);
    gemm_kernel<128, false><<<dim3(BN / 64, 8), 256>>>(nullptr, 128, 512, nullptr, 128, 512, nullptr, nullptr);
    edgemax_kernel<<<BN, 256>>>(g4, b4, 256, 256);

    // ---- w5 GEMM (16384x512x1024) + bn + lrelu + row-block max
    gemm_kernel<512, true><<<dim3(BN / 64, 16), 256>>>(nullptr, 0, 512, w5, 512, 0, g5, b5);
    maxreduce_kernel<<<(B * 1024 + 255) / 256, 256>>>();

    // ---- MLP head
    fc1_kernel<<<(B * 512 + 255) / 256, 256>>>(fw1, fg1, fbt1);
    fc2_kernel<<<(B * 256 + 255) / 256, 256>>>(fw2, fb2, fg2, fbt2);
    fc3_kernel<<<1, 32>>>(fw3, fb3, out);
}

// round 4
// speedup vs baseline: 1.2132x; 1.0871x over previous
#include <cuda_runtime.h>
#include <cstdint>

#define DEVINL __device__ __forceinline__

constexpr int B = 4, N = 4096, K = 10, BN = B * N;
constexpr float SLOPE = 0.2f;
constexpr float BNS = 0.9999950000374997f; // 1/sqrt(1+1e-5)
constexpr float NEG_INF = -3.4e38f;

// packed fp32x2 FMA: acc.lo += a.lo*b.lo, acc.hi += a.hi*b.hi (one issue slot)
DEVINL void fma2(unsigned long long& acc, unsigned long long a, unsigned long long b) {
    asm("fma.rn.f32x2 %0, %1, %2, %0;" : "+l"(acc) : "l"(a), "l"(b));
}
DEVINL float f2sum(unsigned long long v) {
    float2 f = *reinterpret_cast<float2*>(&v);
    return f.x + f.y;
}
struct U64x2 { unsigned long long a, b; };
DEVINL U64x2 asu64x2(const float4& v) {
    U64x2 r;
    r.a = *reinterpret_cast<const unsigned long long*>(&v.x);
    r.b = *reinterpret_cast<const unsigned long long*>(&v.z);
    return r;
}

// ---------------- scratch (static device globals; no allocation) ----------------
__device__ float g_cat[BN * 512];
__device__ float g_AC[BN * 512];
__device__ float g_sq[BN];
__device__ int   g_knn[BN * K];
__device__ float g_wc[512 * 128];
__device__ float g_part[256 * 1024];
__device__ float g_h0[B * 1024];
__device__ float g_y1[B * 512];
__device__ float g_y2[B * 256];

DEVINL const float* x_resolve(const float* xext, int xoff) {
    return xext ? xext : (g_cat + xoff);
}

// ---------------- squared norms ----------------
__global__ void sqnorm_kernel(const float* __restrict__ xext, int xoff, int ldx, int D) {
    int i = blockIdx.x * blockDim.x + threadIdx.x;
    if (i >= BN) return;
    const float* x = x_resolve(xext, xoff);
    const float* p = x + (size_t)i * ldx;
    float s = 0.f;
    for (int d = 0; d < D; ++d) s += p[d] * p[d];
    g_sq[i] = s;
}

// ---------------- weight prep: wc = [w1 ; w2-w1] padded to DPAD ----------------
__global__ void prep_wc_kernel(const float* __restrict__ w, int O, int D, int DPAD) {
    int i = blockIdx.x * blockDim.x + threadIdx.x;
    int total = 2 * O * DPAD;
    if (i >= total) return;
    int r = i / DPAD, d = i % DPAD;
    float v = 0.f;
    if (d < D) {
        if (r < O) v = w[r * 2 * D + d];
        else { int o = r - O; v = w[o * 2 * D + D + d] - w[o * 2 * D + d]; }
    }
    g_wc[i] = v;
}

// ---------------- fused gram + top-k kNN (double-buffered C prefetch) ----------
// block: 256 threads; tile: 64 queries x 32-candidate chunks.
// smem: Q4[64*R4] | C4[2][32*R4] | Ss[64*33]; merge lists alias front (post-loop).
template<int D, int DPAD>
__global__ void __launch_bounds__(256) knn_kernel(const float* __restrict__ xext, int xoff, int ldx) {
    constexpr int R4  = DPAD / 4;
    constexpr int SWM = (R4 >= 8) ? 7 : 0;
    constexpr int CR4 = 32 * R4;
    constexpr int NL  = (CR4 + 255) / 256;
    extern __shared__ __align__(16) char smem[];
    float4* Q4 = (float4*)smem;
    float4* C4 = (float4*)(smem + (size_t)64 * R4 * 16);
    float*  Ss = (float*)(smem + (size_t)64 * R4 * 16 + (size_t)2 * CR4 * 16);
    float*  Mv = (float*)smem;
    int*    Mi = (int*)(smem + 64 * 4 * K * 4);

    const float* x = x_resolve(xext, xoff);
    int tid = threadIdx.x;
    int tx = tid & 15, ty = tid >> 4;
    int rq = tid & 63, rs = tid >> 6;
    int b = blockIdx.y, qbase = blockIdx.x * 64;
    const float* xb  = x + (size_t)b * N * ldx;
    const float* sqb = g_sq + b * N;
    int qglob = qbase + rq;

    float lv[K]; int li[K];
#pragma unroll
    for (int j = 0; j < K; ++j) { lv[j] = NEG_INF; li[j] = 0x7fffffff; }

    // load Q tile (64 x DPAD), xor-swizzled float4 rows
    if constexpr (D == 3) {
        for (int i = tid; i < 64; i += 256) {
            const float* p = xb + (size_t)(qbase + i) * ldx;
            Q4[i] = make_float4(p[0], p[1], p[2], 0.f);
        }
    } else {
        for (int i = tid; i < 64 * R4; i += 256) {
            int row = i / R4, dv = i % R4;
            Q4[row * R4 + (dv ^ (row & SWM))] =
                *(const float4*)(xb + (size_t)(qbase + row) * ldx + dv * 4);
        }
    }

    float4 creg[NL];
    // prefetch of candidate chunk at base cb -> creg
    auto load_c = [&](int cb) {
        if constexpr (D == 3) {
            if (tid < 32) {
                const float* p = xb + (size_t)(cb + tid) * 3;
                creg[0] = make_float4(p[0], p[1], p[2], 0.f);
            }
        } else {
#pragma unroll
            for (int l = 0; l < NL; ++l) {
                int i = tid + l * 256;
                if ((CR4 % 256 == 0) || i < CR4) {
                    int row = i / R4, dv = i % R4;
                    creg[l] = *(const float4*)(xb + (size_t)(cb + row) * ldx + dv * 4);
                }
            }
        }
    };
    auto store_c = [&](int buf) {
        if constexpr (D == 3) {
            if (tid < 32) C4[buf * CR4 + tid] = creg[0];
        } else {
#pragma unroll
            for (int l = 0; l < NL; ++l) {
                int i = tid + l * 256;
                if ((CR4 % 256 == 0) || i < CR4) {
                    int row = i / R4, dv = i % R4;
                    C4[buf * CR4 + row * R4 + (dv ^ (row & SWM))] = creg[l];
                }
            }
        }
    };

    load_c(0);

    for (int cb = 0; cb < N; cb += 32) {
        int buf = (cb >> 5) & 1;
        store_c(buf);
        if (cb + 32 < N) load_c(cb + 32);
        float sc0 = sqb[cb + tx], sc1 = sqb[cb + tx + 16];
        __syncthreads();   // C4[buf] visible; also separates prev top-k reads from Ss writes

        unsigned long long acc2[4][2];
#pragma unroll
        for (int qi = 0; qi < 4; ++qi) { acc2[qi][0] = 0ull; acc2[qi][1] = 0ull; }
        const float4* Cb = C4 + buf * CR4;
#pragma unroll
        for (int dv = 0; dv < R4; ++dv) {
            U64x2 qv[4], cv[2];
#pragma unroll
            for (int qi = 0; qi < 4; ++qi)
                qv[qi] = asu64x2(Q4[(ty + 16 * qi) * R4 + (dv ^ (ty & SWM))]);
#pragma unroll
            for (int ci = 0; ci < 2; ++ci)
                cv[ci] = asu64x2(Cb[(tx + 16 * ci) * R4 + (dv ^ (tx & SWM))]);
#pragma unroll
            for (int qi = 0; qi < 4; ++qi)
#pragma unroll
                for (int ci = 0; ci < 2; ++ci) {
                    fma2(acc2[qi][ci], qv[qi].a, cv[ci].a);
                    fma2(acc2[qi][ci], qv[qi].b, cv[ci].b);
                }
        }
#pragma unroll
        for (int qi = 0; qi < 4; ++qi) {
            Ss[(ty + 16 * qi) * 33 + tx]      = 2.f * f2sum(acc2[qi][0]) - sc0;
            Ss[(ty + 16 * qi) * 33 + tx + 16] = 2.f * f2sum(acc2[qi][1]) - sc1;
        }
        __syncthreads();

        // streaming top-k update: this thread owns query rq, candidates rs*8..rs*8+7
#pragma unroll
        for (int j = 0; j < 8; ++j) {
            int c = cb + rs * 8 + j;
            float v = Ss[rq * 33 + rs * 8 + j];
            if (c != qglob) {
                if (v > lv[K - 1] || (v == lv[K - 1] && c < li[K - 1])) {
                    float cvv = v; int cid = c;
#pragma unroll
                    for (int t = 0; t < K; ++t) {
                        bool better = (cvv > lv[t]) || (cvv == lv[t] && cid < li[t]);
                        float tv = lv[t]; int ti = li[t];
                        if (better) { lv[t] = cvv; li[t] = cid; cvv = tv; cid = ti; }
                    }
                }
            }
        }
    }
    __syncthreads();  // before overwriting smem front with merge lists

    // merge the 4 sorted lists per query
#pragma unroll
    for (int j = 0; j < K; ++j) {
        Mv[(rq * 4 + rs) * K + j] = lv[j];
        Mi[(rq * 4 + rs) * K + j] = li[j];
    }
    __syncthreads();
    if (tid < 64) {
        int h[4] = {0, 0, 0, 0};
        int base = tid * 4 * K;
        int* out = g_knn + (size_t)(b * N + qbase + tid) * K;
        for (int j = 0; j < K; ++j) {
            float bv = NEG_INF; int bi = 0x7fffffff; int bs = 0;
#pragma unroll
            for (int s = 0; s < 4; ++s) {
                if (h[s] < K) {
                    float v = Mv[base + s * K + h[s]];
                    int   i = Mi[base + s * K + h[s]];
                    if (v > bv || (v == bv && i < bi)) { bv = v; bi = i; bs = s; }
                }
            }
            h[bs]++;
            out[j] = bi;
        }
    }
}

// ---------------- register-tiled GEMM (64x64 tile), double-buffered k-chunks ----
template<int DPAD, bool W5MAX>
__global__ void __launch_bounds__(256) gemm_kernel(
    const float* __restrict__ xext, int xoff, int ldx,
    const float* __restrict__ wext, int ldw, int ldo,
    const float* __restrict__ gg, const float* __restrict__ bb)
{
    constexpr int DC  = (DPAD < 32) ? DPAD : 32;
    constexpr int RC  = DC / 4;
    constexpr int SWM = (RC >= 8) ? 7 : 0;
    constexpr int NCH = DPAD / DC;
    constexpr int TR4 = 64 * RC;
    constexpr int NL  = (TR4 + 255) / 256;
    __shared__ float4 Xs[2 * TR4];
    __shared__ float4 Ws[2 * TR4];
    const float* x = x_resolve(xext, xoff);
    const float* w = W5MAX ? wext : g_wc;
    int tid = threadIdx.x, tx = tid & 15, ty = tid >> 4;
    int rowbase = blockIdx.x * 64, colbase = blockIdx.y * 64;
    unsigned long long acc2[4][4];
#pragma unroll
    for (int qi = 0; qi < 4; ++qi)
#pragma unroll
        for (int ci = 0; ci < 4; ++ci) acc2[qi][ci] = 0ull;

    float4 xreg[NL], wreg[NL];
    auto load_xw = [&](int ch) {
        int d0 = ch * DC;
#pragma unroll
        for (int l = 0; l < NL; ++l) {
            int i = tid + l * 256;
            if ((TR4 % 256 == 0) || i < TR4) {
                int r = i / RC, dv = i % RC;
                if constexpr (DPAD == 4) {
                    const float* p = x + (size_t)(rowbase + r) * ldx;  // ldx may be 3
                    xreg[l] = make_float4(p[0], p[1], p[2], 0.f);
                } else {
                    xreg[l] = *(const float4*)(x + (size_t)(rowbase + r) * ldx + d0 + 4 * dv);
                }
                wreg[l] = *(const float4*)(w + (size_t)(colbase + r) * ldw + d0 + 4 * dv);
            }
        }
    };
    auto store_xw = [&](int buf) {
#pragma unroll
        for (int l = 0; l < NL; ++l) {
            int i = tid + l * 256;
            if ((TR4 % 256 == 0) || i < TR4) {
                int r = i / RC, dv = i % RC;
                Xs[buf * TR4 + r * RC + (dv ^ (r & SWM))] = xreg[l];
                Ws[buf * TR4 + r * RC + (dv ^ (r & SWM))] = wreg[l];
            }
        }
    };

    load_xw(0);
    for (int ch = 0; ch < NCH; ++ch) {
        int buf = ch & 1;
        store_xw(buf);
        if (ch + 1 < NCH) load_xw(ch + 1);
        __syncthreads();
        const float4* Xb = Xs + buf * TR4;
        const float4* Wb = Ws + buf * TR4;
#pragma unroll
        for (int dv = 0; dv < RC; ++dv) {
            U64x2 xv[4], wv[4];
#pragma unroll
            for (int qi = 0; qi < 4; ++qi)
                xv[qi] = asu64x2(Xb[(ty + 16 * qi) * RC + (dv ^ (ty & SWM))]);
#pragma unroll
            for (int ci = 0; ci < 4; ++ci)
                wv[ci] = asu64x2(Wb[(tx + 16 * ci) * RC + (dv ^ (tx & SWM))]);
#pragma unroll
            for (int qi = 0; qi < 4; ++qi)
#pragma unroll
                for (int ci = 0; ci < 4; ++ci) {
                    fma2(acc2[qi][ci], xv[qi].a, wv[ci].a);
                    fma2(acc2[qi][ci], xv[qi].b, wv[ci].b);
                }
        }
        __syncthreads();
    }

    if constexpr (!W5MAX) {
#pragma unroll
        for (int qi = 0; qi < 4; ++qi)
#pragma unroll
            for (int ci = 0; ci < 4; ++ci)
                g_AC[(size_t)(rowbase + ty + 16 * qi) * ldo + colbase + tx + 16 * ci] =
                    f2sum(acc2[qi][ci]);
    } else {
        float cm[4];
#pragma unroll
        for (int ci = 0; ci < 4; ++ci) {
            int col = colbase + tx + 16 * ci;
            float g = BNS * gg[col], be = bb[col];
            float m = NEG_INF;
#pragma unroll
            for (int qi = 0; qi < 4; ++qi) {
                float v = g * f2sum(acc2[qi][ci]) + be;
                v = (v > 0.f) ? v : SLOPE * v;
                m = fmaxf(m, v);
            }
            cm[ci] = m;
        }
        float* R = (float*)Xs;  // 16x64 floats; W5MAX has RC=8 so Xs is big enough
#pragma unroll
        for (int ci = 0; ci < 4; ++ci) R[ty * 64 + tx + 16 * ci] = cm[ci];
        __syncthreads();
        if (tid < 64) {
            float m = R[tid];
#pragma unroll
            for (int t = 1; t < 16; ++t) m = fmaxf(m, R[t * 64 + tid]);
            g_part[(size_t)blockIdx.x * 1024 + colbase + tid] = m;
        }
    }
}

// ---------------- gather + bn + lrelu + max over k neighbors ----------------
__global__ void edgemax_kernel(const float* __restrict__ gamma, const float* __restrict__ beta,
                               int O, int catoff) {
    int n = blockIdx.x;
    int o = threadIdx.x;
    int b = n >> 12;
    __shared__ int sidx[K];
    if (o < K) sidx[o] = g_knn[(size_t)n * K + o];
    __syncthreads();
    int twoO = 2 * O;
    float cterm = g_AC[(size_t)n * twoO + O + o];
    float g = BNS * gamma[o], be = beta[o];
    int base = b << 12;
    float m = NEG_INF;
#pragma unroll
    for (int j = 0; j < K; ++j) {
        float a = g_AC[(size_t)(base + sidx[j]) * twoO + o];
        float v = g * (a + cterm) + be;
        v = (v > 0.f) ? v : SLOPE * v;
        m = fmaxf(m, v);
    }
    g_cat[(size_t)n * 512 + catoff + o] = m;
}

// ---------------- final max reduce + MLP head ----------------
__global__ void maxreduce_kernel() {
    int i = blockIdx.x * blockDim.x + threadIdx.x;
    if (i >= B * 1024) return;
    int b = i / 1024, o = i % 1024;
    float m = NEG_INF;
    for (int j = 0; j < 64; ++j)
        m = fmaxf(m, g_part[(size_t)(b * 64 + j) * 1024 + o]);
    g_h0[i] = m;
}

__global__ void fc1_kernel(const float* __restrict__ fw1, const float* __restrict__ fg1,
                           const float* __restrict__ fbt1) {
    int t = blockIdx.x * blockDim.x + threadIdx.x;
    if (t >= B * 512) return;
    int b = t / 512, o = t % 512;
    const float* h = g_h0 + b * 1024;
    const float* wr = fw1 + (size_t)o * 1024;
    float s = 0.f;
    for (int c = 0; c < 1024; ++c) s += h[c] * wr[c];
    float v = BNS * fg1[o] * s + fbt1[o];
    g_y1[t] = (v > 0.f) ? v : SLOPE * v;
}

__global__ void fc2_kernel(const float* __restrict__ fw2, const float* __restrict__ fb2,
                           const float* __restrict__ fg2, const float* __restrict__ fbt2) {
    int t = blockIdx.x * blockDim.x + threadIdx.x;
    if (t >= B * 256) return;
    int b = t / 256, o = t % 256;
    const float* h = g_y1 + b * 512;
    const float* wr = fw2 + (size_t)o * 512;
    float s = 0.f;
    for (int c = 0; c < 512; ++c) s += h[c] * wr[c];
    float v = BNS * fg2[o] * (s + fb2[o]) + fbt2[o];
    g_y2[t] = (v > 0.f) ? v : SLOPE * v;
}

__global__ void fc3_kernel(const float* __restrict__ fw3, const float* __restrict__ fb3,
                           float* __restrict__ out) {
    int t = blockIdx.x * blockDim.x + threadIdx.x;
    if (t >= B * 3) return;
    int b = t / 3, o = t % 3;
    const float* h = g_y2 + b * 256;
    const float* wr = fw3 + (size_t)o * 256;
    float s = 0.f;
    for (int c = 0; c < 256; ++c) s += h[c] * wr[c];
    out[t] = s + fb3[o];
}

// ---------------- launch ----------------
static int knn_smem_bytes(int R4) {
    int s = 64 * R4 * 16 + 2 * 32 * R4 * 16 + 64 * 33 * 4;
    int merge = 64 * 4 * K * 8;
    return s > merge ? s : merge;
}

extern "C" void kernel_launch(void* const* d_in, const int* in_sizes, int n_in,
                              void* d_out, int out_size) {
    const float* points = (const float*)d_in[0];
    const float* w1 = (const float*)d_in[2];
    const float* g1 = (const float*)d_in[3];
    const float* b1 = (const float*)d_in[4];
    const float* w2 = (const float*)d_in[5];
    const float* g2 = (const float*)d_in[6];
    const float* b2 = (const float*)d_in[7];
    const float* w3 = (const float*)d_in[8];
    const float* g3 = (const float*)d_in[9];
    const float* b3 = (const float*)d_in[10];
    const float* w4 = (const float*)d_in[11];
    const float* g4 = (const float*)d_in[12];
    const float* b4 = (const float*)d_in[13];
    const float* w5 = (const float*)d_in[14];
    const float* g5 = (const float*)d_in[15];
    const float* b5 = (const float*)d_in[16];
    const float* fw1 = (const float*)d_in[17];
    const float* fg1 = (const float*)d_in[18];
    const float* fbt1 = (const float*)d_in[19];
    const float* fw2 = (const float*)d_in[20];
    const float* fb2 = (const float*)d_in[21];
    const float* fg2 = (const float*)d_in[22];
    const float* fbt2 = (const float*)d_in[23];
    const float* fw3 = (const float*)d_in[24];
    const float* fb3 = (const float*)d_in[25];
    float* out = (float*)d_out;

    dim3 knngrid(N / 64, B);
    int sm1 = knn_smem_bytes(1);
    int sm16 = knn_smem_bytes(16);
    int sm32 = knn_smem_bytes(32);
    static bool attr_done = false;
    if (!attr_done) {
        cudaFuncSetAttribute(knn_kernel<128, 128>, cudaFuncAttributeMaxDynamicSharedMemorySize, sm32);
        cudaFuncSetAttribute(knn_kernel<64, 64>, cudaFuncAttributeMaxDynamicSharedMemorySize, sm16);
        cudaFuncSetAttribute(knn_kernel<3, 4>, cudaFuncAttributeMaxDynamicSharedMemorySize, sm1);
        attr_done = true;
    }

    // ---- EdgeConv 1: x = points (ld 3, D=3), O=64, cat cols [0,64)
    sqnorm_kernel<<<BN / 256, 256>>>(points, 0, 3, 3);
    knn_kernel<3, 4><<<knngrid, 256, sm1>>>(points, 0, 3);
    prep_wc_kernel<<<(2 * 64 * 4 + 255) / 256, 256>>>(w1, 64, 3, 4);
    gemm_kernel<4, false><<<dim3(BN / 64, 2), 256>>>(points, 0, 3, nullptr, 4, 128, nullptr, nullptr);
    edgemax_kernel<<<BN, 64>>>(g1, b1, 64, 0);

    // ---- EdgeConv 2: x = cat[:,0:64], O=64, cat cols [64,128)
    sqnorm_kernel<<<BN / 256, 256>>>(nullptr, 0, 512, 64);
    knn_kernel<64, 64><<<knngrid, 256, sm16>>>(nullptr, 0, 512);
    prep_wc_kernel<<<(2 * 64 * 64 + 255) / 256, 256>>>(w2, 64, 64, 64);
    gemm_kernel<64, false><<<dim3(BN / 64, 2), 256>>>(nullptr, 0, 512, nullptr, 64, 128, nullptr, nullptr);
    edgemax_kernel<<<BN, 64>>>(g2, b2, 64, 64);

    // ---- EdgeConv 3: x = cat[:,64:128], O=128, cat cols [128,256)
    sqnorm_kernel<<<BN / 256, 256>>>(nullptr, 64, 512, 64);
    knn_kernel<64, 64><<<knngrid, 256, sm16>>>(nullptr, 64, 512);
    prep_wc_kernel<<<(2 * 128 * 64 + 255) / 256, 256>>>(w3, 128, 64, 64);
    gemm_kernel<64, false><<<dim3(BN / 64, 4), 256>>>(nullptr, 64, 512, nullptr, 64, 256, nullptr, nullptr);
    edgemax_kernel<<<BN, 128>>>(g3, b3, 128, 128);

    // ---- EdgeConv 4: x = cat[:,128:256], D=128, O=256, cat cols [256,512)
    sqnorm_kernel<<<BN / 256, 256>>>(nullptr, 128, 512, 128);
    knn_kernel<128, 128><<<knngrid, 256, sm32>>>(nullptr, 128, 512);
    prep_wc_kernel<<<(2 * 256 * 128 + 255) / 256, 256>>>(w4, 256, 128, 128);
    gemm_kernel<128, false><<<dim3(BN / 64, 8), 256>>>(nullptr, 128, 512, nullptr, 128, 512, nullptr, nullptr);
    edgemax_kernel<<<BN, 256>>>(g4, b4, 256, 256);

    // ---- w5 GEMM (16384x512x1024) + bn + lrelu + row-block max
    gemm_kernel<512, true><<<dim3(BN / 64, 16), 256>>>(nullptr, 0, 512, w5, 512, 0, g5, b5);
    maxreduce_kernel<<<(B * 1024 + 255) / 256, 256>>>();

    // ---- MLP head
    fc1_kernel<<<(B * 512 + 255) / 256, 256>>>(fw1, fg1, fbt1);
    fc2_kernel<<<(B * 256 + 255) / 256, 256>>>(fw2, fb2, fg2, fbt2);
    fc3_kernel<<<1, 32>>>(fw3, fb3, out);
}